// round 9
// baseline (speedup 1.0000x reference)
#include <cuda_runtime.h>
#include <math.h>

#define NN 50000
#define EE 800000
#define GG 50

// ---------------- scratch (device globals: allocation-free) ----------------
__device__ float g_h[NN * 256];      // pre-aggregation features (per layer)
__device__ float g_o[NN * 256];      // aggregated output (per layer)
__device__ float g_aS[NN * 4];       // per-node att-src coefficients
__device__ float g_aD[NN * 4];       // per-node att-dst coefficients
__device__ float g_pool[GG * 256];
__device__ int   g_deg[NN];
__device__ int   g_off[NN + 1];
__device__ int   g_cur[NN];
__device__ int   g_csr[EE];          // src node per edge, grouped by dst

// ---------------- packed f32x2 helpers (Blackwell FFMA2 path) --------------
__device__ __forceinline__ unsigned long long pk2(float lo, float hi) {
    unsigned long long r;
    asm("mov.b64 %0, {%1, %2};" : "=l"(r) : "f"(lo), "f"(hi));
    return r;
}
__device__ __forceinline__ float2 upk2(unsigned long long v) {
    float2 r;
    asm("mov.b64 {%0, %1}, %2;" : "=f"(r.x), "=f"(r.y) : "l"(v));
    return r;
}
__device__ __forceinline__ void fma2(unsigned long long &d,
                                     unsigned long long a,
                                     unsigned long long b) {
    asm("fma.rn.f32x2 %0, %1, %2, %0;" : "+l"(d) : "l"(a), "l"(b));
}

// ---------------- CSR build ----------------
__global__ void deg_kernel(const int* __restrict__ dst, int* __restrict__ deg, int E) {
    int i = blockIdx.x * blockDim.x + threadIdx.x;
    if (i < E) atomicAdd(&deg[dst[i]], 1);
}

__global__ void scan_kernel(const int* __restrict__ deg, int* __restrict__ off,
                            int* __restrict__ cur, int N) {
    __shared__ int sm[1024];
    __shared__ int s_carry;
    int tid = threadIdx.x;
    if (tid == 0) s_carry = 0;
    __syncthreads();
    for (int base = 0; base < N; base += 1024) {
        int idx = base + tid;
        int v = (idx < N) ? deg[idx] : 0;
        sm[tid] = v;
        __syncthreads();
        for (int d = 1; d < 1024; d <<= 1) {
            int t = (tid >= d) ? sm[tid - d] : 0;
            __syncthreads();
            sm[tid] += t;
            __syncthreads();
        }
        int inc = sm[tid];
        int carry = s_carry;
        int excl = carry + inc - v;
        if (idx < N) { off[idx] = excl; cur[idx] = excl; }
        __syncthreads();
        if (tid == 1023) s_carry = carry + inc;
        __syncthreads();
    }
    if (tid == 0) off[N] = s_carry;
}

__global__ void fill_kernel(const int* __restrict__ src, const int* __restrict__ dst,
                            int* __restrict__ cur, int* __restrict__ csr, int E) {
    int i = blockIdx.x * blockDim.x + threadIdx.x;
    if (i < E) {
        int p = atomicAdd(&cur[dst[i]], 1);
        csr[p] = src[i];
    }
}

// ---------------- SGEMM: C[N,256] = A[N,256] @ B[256,256], fp32 via f32x2 ---
__global__ void __launch_bounds__(256, 2)
sgemm256(const float* __restrict__ A, const float* __restrict__ B,
         float* __restrict__ C, int N) {
    __shared__ __align__(16) float As[16][128];   // transposed A tile
    __shared__ __align__(16) float Bs[16][128];
    int tid = threadIdx.x;
    int brow = blockIdx.x * 128;
    int bcol = blockIdx.y * 128;
    int trow = (tid >> 4) << 3;   // 0..120
    int tcol = (tid & 15) << 3;   // 0..120

    unsigned long long acc[8][4];
#pragma unroll
    for (int m = 0; m < 8; ++m)
#pragma unroll
        for (int n = 0; n < 4; ++n) acc[m][n] = 0ull;

    for (int kt = 0; kt < 256; kt += 16) {
#pragma unroll
        for (int i = 0; i < 2; ++i) {
            int f = tid + (i << 8);
            int ar = f >> 2;
            int ak = (f & 3) << 2;
            int grow = brow + ar;
            float4 v = make_float4(0.f, 0.f, 0.f, 0.f);
            if (grow < N) v = *(const float4*)(A + (size_t)grow * 256 + kt + ak);
            As[ak + 0][ar] = v.x;
            As[ak + 1][ar] = v.y;
            As[ak + 2][ar] = v.z;
            As[ak + 3][ar] = v.w;
        }
#pragma unroll
        for (int i = 0; i < 2; ++i) {
            int f = tid + (i << 8);
            int bk = f >> 5;
            int bn = (f & 31) << 2;
            *(float4*)(&Bs[bk][bn]) =
                *(const float4*)(B + (size_t)(kt + bk) * 256 + bcol + bn);
        }
        __syncthreads();
#pragma unroll
        for (int k = 0; k < 16; ++k) {
            float4 a0 = *(const float4*)(&As[k][trow]);
            float4 a1 = *(const float4*)(&As[k][trow + 4]);
            float4 b0 = *(const float4*)(&Bs[k][tcol]);
            float4 b1 = *(const float4*)(&Bs[k][tcol + 4]);
            unsigned long long bq[4];
            bq[0] = pk2(b0.x, b0.y);
            bq[1] = pk2(b0.z, b0.w);
            bq[2] = pk2(b1.x, b1.y);
            bq[3] = pk2(b1.z, b1.w);
            float av[8] = {a0.x, a0.y, a0.z, a0.w, a1.x, a1.y, a1.z, a1.w};
#pragma unroll
            for (int m = 0; m < 8; ++m) {
                unsigned long long am = pk2(av[m], av[m]);
#pragma unroll
                for (int n = 0; n < 4; ++n) fma2(acc[m][n], am, bq[n]);
            }
        }
        __syncthreads();
    }
#pragma unroll
    for (int m = 0; m < 8; ++m) {
        int grow = brow + trow + m;
        if (grow < N) {
            float2 c0 = upk2(acc[m][0]);
            float2 c1 = upk2(acc[m][1]);
            float2 c2 = upk2(acc[m][2]);
            float2 c3 = upk2(acc[m][3]);
            float* cp = C + (size_t)grow * 256 + bcol + tcol;
            *(float4*)cp       = make_float4(c0.x, c0.y, c1.x, c1.y);
            *(float4*)(cp + 4) = make_float4(c2.x, c2.y, c3.x, c3.y);
        }
    }
}

// ---------------- per-node attention coefficients --------------------------
// a_src[n,h] = dot(h[n, h*C:(h+1)*C], att_src[h]); lane owns 8 contiguous cols
__global__ void __launch_bounds__(256)
attn_kernel(const float* __restrict__ h, const float* __restrict__ attS,
            const float* __restrict__ attD, float* __restrict__ aS,
            float* __restrict__ aD, int N, int H) {
    int warp = (blockIdx.x * blockDim.x + threadIdx.x) >> 5;
    if (warp >= N) return;
    int lane = threadIdx.x & 31;
    const float4* hp = (const float4*)(h + (size_t)warp * 256);
    float4 h0 = hp[lane * 2], h1 = hp[lane * 2 + 1];
    const float4* sp = (const float4*)attS;
    const float4* dp = (const float4*)attD;
    float4 s0 = sp[lane * 2], s1 = sp[lane * 2 + 1];
    float4 d0 = dp[lane * 2], d1 = dp[lane * 2 + 1];
    float ps = h0.x * s0.x + h0.y * s0.y + h0.z * s0.z + h0.w * s0.w
             + h1.x * s1.x + h1.y * s1.y + h1.z * s1.z + h1.w * s1.w;
    float pd = h0.x * d0.x + h0.y * d0.y + h0.z * d0.z + h0.w * d0.w
             + h1.x * d1.x + h1.y * d1.y + h1.z * d1.z + h1.w * d1.w;
    int gsz = 32 / H;   // lanes per head
    for (int o = gsz >> 1; o > 0; o >>= 1) {
        ps += __shfl_xor_sync(0xffffffffu, ps, o);
        pd += __shfl_xor_sync(0xffffffffu, pd, o);
    }
    if ((lane & (gsz - 1)) == 0) {
        int head = lane / gsz;
        aS[warp * H + head] = ps;
        aD[warp * H + head] = pd;
    }
}

// ---------------- GAT aggregation: one warp per dst node -------------------
// pass1: online softmax (per-lane, per-head).  pass2: weighted feature gather.
__global__ void __launch_bounds__(256)
aggregate_kernel(const float* __restrict__ h, const float* __restrict__ aS,
                 const float* __restrict__ aD, const float* __restrict__ bias,
                 float* __restrict__ out, int N, int H) {
    int warp = (blockIdx.x * blockDim.x + threadIdx.x) >> 5;
    if (warp >= N) return;
    int lane = threadIdx.x & 31;
    int head = (lane * H) >> 5;          // H=4 -> lane/8, H=1 -> 0
    int beg = g_off[warp];
    int end = g_off[warp + 1];
    float adst = aD[warp * H + head];

    float m = -INFINITY, s = 0.f;
    for (int j = beg; j < end; ++j) {
        int src = __ldg(&g_csr[j]);
        float e = __ldg(&aS[src * H + head]) + adst;
        e = (e > 0.f) ? e : 0.2f * e;
        float mn = fmaxf(m, e);
        s = s * __expf(m - mn) + __expf(e - mn);
        m = mn;
    }
    float inv_s = (s > 0.f) ? (1.f / s) : 0.f;

    float4 acc0 = make_float4(0.f, 0.f, 0.f, 0.f);
    float4 acc1 = make_float4(0.f, 0.f, 0.f, 0.f);
    for (int j = beg; j < end; ++j) {
        int src = __ldg(&g_csr[j]);
        float e = __ldg(&aS[src * H + head]) + adst;
        e = (e > 0.f) ? e : 0.2f * e;
        float w = __expf(e - m) * inv_s;
        const float4* hp = (const float4*)(h + (size_t)src * 256 + lane * 8);
        float4 v0 = __ldg(hp);
        float4 v1 = __ldg(hp + 1);
        acc0.x += w * v0.x; acc0.y += w * v0.y; acc0.z += w * v0.z; acc0.w += w * v0.w;
        acc1.x += w * v1.x; acc1.y += w * v1.y; acc1.z += w * v1.z; acc1.w += w * v1.w;
    }
    const float4* bp = (const float4*)(bias + lane * 8);
    float4 b0 = bp[0], b1 = bp[1];
    float4 o0, o1;
    o0.x = fmaxf(acc0.x + b0.x, 0.f); o0.y = fmaxf(acc0.y + b0.y, 0.f);
    o0.z = fmaxf(acc0.z + b0.z, 0.f); o0.w = fmaxf(acc0.w + b0.w, 0.f);
    o1.x = fmaxf(acc1.x + b1.x, 0.f); o1.y = fmaxf(acc1.y + b1.y, 0.f);
    o1.z = fmaxf(acc1.z + b1.z, 0.f); o1.w = fmaxf(acc1.w + b1.w, 0.f);
    float4* op = (float4*)(out + (size_t)warp * 256 + lane * 8);
    op[0] = o0;
    op[1] = o1;
}

// ---------------- pooling: one block per graph (batch is sorted) -----------
__device__ __forceinline__ int lower_bound_dev(const int* __restrict__ a, int n, int key) {
    int lo = 0, hi = n;
    while (lo < hi) {
        int mid = (lo + hi) >> 1;
        if (__ldg(&a[mid]) < key) lo = mid + 1; else hi = mid;
    }
    return lo;
}

__global__ void pool_kernel(const float* __restrict__ h, const int* __restrict__ batch,
                            float* __restrict__ pooled, int N, int G) {
    int g = blockIdx.x;
    int c = threadIdx.x;
    int lo = lower_bound_dev(batch, N, g);
    int hi = lower_bound_dev(batch, N, g + 1);
    float acc = 0.f;
#pragma unroll 4
    for (int n = lo; n < hi; ++n) acc += __ldg(&h[(size_t)n * 256 + c]);
    int cnt = hi - lo;
    float denom = (cnt > 0) ? (float)cnt : 1.f;
    pooled[g * 256 + c] = acc / denom;
}

// ---------------- final FC + relu ------------------------------------------
__global__ void fc_kernel(const float* __restrict__ pooled, const float* __restrict__ W,
                          const float* __restrict__ b, float* __restrict__ out, int G) {
    int g = blockIdx.x;
    int o = threadIdx.x;
    __shared__ float p[256];
    p[o] = pooled[g * 256 + o];
    __syncthreads();
    float acc = b[o];
#pragma unroll 8
    for (int i = 0; i < 256; ++i) acc += p[i] * W[i * 256 + o];
    out[g * 256 + o] = fmaxf(acc, 0.f);
}

// ---------------- launch ----------------------------------------------------
extern "C" void kernel_launch(void* const* d_in, const int* in_sizes, int n_in,
                              void* d_out, int out_size) {
    const float* x     = (const float*)d_in[0];
    const int*   ei    = (const int*)  d_in[1];
    const int*   batch = (const int*)  d_in[2];
    const float* W1    = (const float*)d_in[3];
    const float* attS1 = (const float*)d_in[4];
    const float* attD1 = (const float*)d_in[5];
    const float* b1    = (const float*)d_in[6];
    const float* W2    = (const float*)d_in[7];
    const float* attS2 = (const float*)d_in[8];
    const float* attD2 = (const float*)d_in[9];
    const float* b2    = (const float*)d_in[10];
    const float* Wfc   = (const float*)d_in[11];
    const float* bfc   = (const float*)d_in[12];
    float* outp = (float*)d_out;

    int N = in_sizes[0] / 256;
    int E = in_sizes[1] / 2;
    int G = out_size / 256;
    const int* src = ei;
    const int* dst = ei + E;

    float *hbuf, *obuf, *aS, *aD, *pooled;
    int *deg, *off, *cur, *csr;
    cudaGetSymbolAddress((void**)&hbuf, g_h);
    cudaGetSymbolAddress((void**)&obuf, g_o);
    cudaGetSymbolAddress((void**)&aS,   g_aS);
    cudaGetSymbolAddress((void**)&aD,   g_aD);
    cudaGetSymbolAddress((void**)&pooled, g_pool);
    cudaGetSymbolAddress((void**)&deg, g_deg);
    cudaGetSymbolAddress((void**)&off, g_off);
    cudaGetSymbolAddress((void**)&cur, g_cur);
    cudaGetSymbolAddress((void**)&csr, g_csr);

    int eb = (E + 255) / 256;            // edge-parallel blocks
    int wb = (N + 7) / 8;                // warp-per-node blocks (256 thr = 8 warps)
    dim3 ggrid((N + 127) / 128, 2);      // GEMM grid

    // CSR build (by dst)
    cudaMemsetAsync(deg, 0, (size_t)N * sizeof(int));
    deg_kernel<<<eb, 256>>>(dst, deg, E);
    scan_kernel<<<1, 1024>>>(deg, off, cur, N);
    fill_kernel<<<eb, 256>>>(src, dst, cur, csr, E);

    // Layer 1 (H=4, C=64)
    sgemm256<<<ggrid, 256>>>(x, W1, hbuf, N);
    attn_kernel<<<wb, 256>>>(hbuf, attS1, attD1, aS, aD, N, 4);
    aggregate_kernel<<<wb, 256>>>(hbuf, aS, aD, b1, obuf, N, 4);

    // Layer 2 (H=1, C=256)
    sgemm256<<<ggrid, 256>>>(obuf, W2, hbuf, N);
    attn_kernel<<<wb, 256>>>(hbuf, attS2, attD2, aS, aD, N, 1);
    aggregate_kernel<<<wb, 256>>>(hbuf, aS, aD, b2, obuf, N, 1);

    // Pool + FC
    pool_kernel<<<G, 256>>>(obuf, batch, pooled, N, G);
    fc_kernel<<<G, 256>>>(pooled, Wfc, bfc, outp, G);
}